// round 4
// baseline (speedup 1.0000x reference)
#include <cuda_runtime.h>
#include <math.h>

// x: [2048, 512, 7, 7] fp32.
#define NCH      512
#define HW       49
#define SLAB     (NCH * HW)      // 25088 floats / sample
#define SLAB4    (SLAB / 4)      // 6272 float4 / sample
#define NTHREADS 512
#define NWARPS   (NTHREADS / 32) // 16
#define CH_PER_W (NCH / NWARPS)  // 32 channels per warp
#define EPS      1e-5f
#define GRID     592             // 4 CTAs/SM * 148 SMs (persistent)

// SLAB4 = 512*12 + 128
#define FULL_BATCHES 3           // 3 batches of 4 strided iterations = 12
#define REM_THREADS  128

__global__ __launch_bounds__(NTHREADS, 4)
void ModelNew_25056839205377_kernel(const float* __restrict__ x,
                                    float* __restrict__ out,
                                    int nsamples)
{
    __shared__ float ch[NCH + 1];   // y[c], later gate[c]; +1 slack for c+1 read
    __shared__ float red[34];       // 16 sums, 16 sumsqs, 2 bcast

    const int tid  = threadIdx.x;
    const int warp = tid >> 5;
    const int lane = tid & 31;

    for (int smp = blockIdx.x; smp < nsamples; smp += GRID) {
        const size_t base = (size_t)smp * SLAB;
        const float* __restrict__ xp = x + base;

        // ---- Phase 1: y[c] = spatial mean. Each warp owns 32 channels. ----
        // Default (caching) loads: lines must stay in L2 for the phase-4 re-read.
        #pragma unroll 4
        for (int k = 0; k < CH_PER_W; ++k) {
            const int c = warp * CH_PER_W + k;
            const float* p = xp + c * HW;
            float s = p[lane] + ((lane < HW - 32) ? p[32 + lane] : 0.0f);
            #pragma unroll
            for (int o = 16; o > 0; o >>= 1)
                s += __shfl_xor_sync(0xffffffffu, s, o);
            if (lane == 0) ch[c] = s * (1.0f / HW);
        }
        __syncthreads();

        // ---- Phase 2: stats over 512 channels (thread c owns channel c) ----
        const float y = ch[tid];
        float ys = y, y2 = y * y;
        #pragma unroll
        for (int o = 16; o > 0; o >>= 1) {
            ys += __shfl_xor_sync(0xffffffffu, ys, o);
            y2 += __shfl_xor_sync(0xffffffffu, y2, o);
        }
        if (lane == 0) { red[warp] = ys; red[16 + warp] = y2; }
        __syncthreads();
        if (warp == 0) {
            float s1 = (lane < 16) ? red[lane]      : 0.0f;
            float s2 = (lane < 16) ? red[16 + lane] : 0.0f;
            #pragma unroll
            for (int o = 8; o > 0; o >>= 1) {
                s1 += __shfl_xor_sync(0xffffffffu, s1, o);
                s2 += __shfl_xor_sync(0xffffffffu, s2, o);
            }
            if (lane == 0) {
                const float m   = s1 * (1.0f / NCH);
                const float mx2 = s2 * (1.0f / NCH);
                const float var = fmaxf(mx2 - m * m, 0.0f);
                red[32] = m;
                red[33] = rsqrtf(var + EPS);
            }
        }
        __syncthreads();

        // ---- Phase 3: gate[c] = exp(-z^2)  (C_PARAM=2) ----
        {
            const float m   = red[32];
            const float inv = red[33];
            const float z   = (y - m) * inv;
            ch[tid] = __expf(-z * z);
        }
        if (tid == 0) ch[NCH] = 0.0f;
        __syncthreads();

        // ---- Phase 4: re-read x (L2-hit, evict-first), gate, stream store ----
        const float4* __restrict__ x4 = (const float4*)xp;
        float4* __restrict__ o4 = (float4*)(out + base);

        #pragma unroll
        for (int b = 0; b < FULL_BATCHES; ++b) {
            const int i0 = tid + (4 * b) * NTHREADS;
            // batch 4 independent 128b loads up front (MLP)
            float4 v0 = __ldcs(x4 + i0 + 0 * NTHREADS);
            float4 v1 = __ldcs(x4 + i0 + 1 * NTHREADS);
            float4 v2 = __ldcs(x4 + i0 + 2 * NTHREADS);
            float4 v3 = __ldcs(x4 + i0 + 3 * NTHREADS);
            #pragma unroll
            for (int k = 0; k < 4; ++k) {
                float4& v = (k == 0) ? v0 : (k == 1) ? v1 : (k == 2) ? v2 : v3;
                const int e = (i0 + k * NTHREADS) * 4;
                const int c = e / HW;
                const int r = e - c * HW;
                const float g0 = ch[c];
                const float gn = ch[c + 1];
                v.x *= g0;
                v.y *= (r < 48) ? g0 : gn;
                v.z *= (r < 47) ? g0 : gn;
                v.w *= (r < 46) ? g0 : gn;
                __stcs(o4 + i0 + k * NTHREADS, v);
            }
        }
        // remainder: SLAB4 - 12*512 = 128 elements
        if (tid < REM_THREADS) {
            const int i = tid + 12 * NTHREADS;
            float4 v = __ldcs(x4 + i);
            const int e = i * 4;
            const int c = e / HW;
            const int r = e - c * HW;
            const float g0 = ch[c];
            const float gn = ch[c + 1];
            v.x *= g0;
            v.y *= (r < 48) ? g0 : gn;
            v.z *= (r < 47) ? g0 : gn;
            v.w *= (r < 46) ? g0 : gn;
            __stcs(o4 + i, v);
        }
        __syncthreads();   // protect ch[] before next sample's phase 1
    }
}

extern "C" void kernel_launch(void* const* d_in, const int* in_sizes, int n_in,
                              void* d_out, int out_size)
{
    const float* x = (const float*)d_in[0];
    float* out = (float*)d_out;
    const int nsamples = in_sizes[0] / SLAB;   // 2048
    ModelNew_25056839205377_kernel<<<GRID, NTHREADS>>>(x, out, nsamples);
}

// round 5
// speedup vs baseline: 1.4345x; 1.4345x over previous
#include <cuda_runtime.h>
#include <math.h>

// x: [2048, 512, 7, 7] fp32.
#define NCH      512
#define HW       49
#define SLAB     (NCH * HW)      // 25088 floats / sample
#define SLAB4    (SLAB / 4)      // 6272 float4 / sample
#define NTHREADS 512
#define NWARPS   (NTHREADS / 32) // 16
#define CH_PER_W (NCH / NWARPS)  // 32 channels per warp
#define EPS      1e-5f

// SLAB4 = 512*12 + 128
#define FULL_BATCHES 3
#define REM_THREADS  128

__global__ __launch_bounds__(NTHREADS, 4)
void ModelNew_25056839205377_kernel(const float* __restrict__ x,
                                    float* __restrict__ out)
{
    __shared__ float ch[NCH + 1];   // y[c], later gate[c]; +1 slack for c+1 read
    __shared__ float red[34];       // 16 sums, 16 sumsqs, 2 bcast

    const int tid  = threadIdx.x;
    const int warp = tid >> 5;
    const int lane = tid & 31;
    const size_t base = (size_t)blockIdx.x * SLAB;
    const float* __restrict__ xp = x + base;

    // ---- Phase 1: y[c] = spatial mean. Each warp owns 32 channels. ----
    // unroll 8: 8 independent shuffle-reduction chains hide SHFL latency.
    #pragma unroll 8
    for (int k = 0; k < CH_PER_W; ++k) {
        const int c = warp * CH_PER_W + k;
        const float* p = xp + c * HW;
        float s = p[lane] + ((lane < HW - 32) ? p[32 + lane] : 0.0f);
        #pragma unroll
        for (int o = 16; o > 0; o >>= 1)
            s += __shfl_xor_sync(0xffffffffu, s, o);
        if (lane == 0) ch[c] = s * (1.0f / HW);
    }
    __syncthreads();

    // ---- Phase 2: stats over 512 channels (thread c owns channel c) ----
    const float y = ch[tid];
    float ys = y, y2 = y * y;
    #pragma unroll
    for (int o = 16; o > 0; o >>= 1) {
        ys += __shfl_xor_sync(0xffffffffu, ys, o);
        y2 += __shfl_xor_sync(0xffffffffu, y2, o);
    }
    if (lane == 0) { red[warp] = ys; red[16 + warp] = y2; }
    __syncthreads();
    if (warp == 0) {
        float s1 = (lane < 16) ? red[lane]      : 0.0f;
        float s2 = (lane < 16) ? red[16 + lane] : 0.0f;
        #pragma unroll
        for (int o = 8; o > 0; o >>= 1) {
            s1 += __shfl_xor_sync(0xffffffffu, s1, o);
            s2 += __shfl_xor_sync(0xffffffffu, s2, o);
        }
        if (lane == 0) {
            const float m   = s1 * (1.0f / NCH);
            const float mx2 = s2 * (1.0f / NCH);
            const float var = fmaxf(mx2 - m * m, 0.0f);
            red[32] = m;
            red[33] = rsqrtf(var + EPS);
        }
    }
    __syncthreads();

    // ---- Phase 3: gate[c] = exp(-z^2)  (C_PARAM=2 -> -0.5*2*z^2 = -z^2) ----
    {
        const float m   = red[32];
        const float inv = red[33];
        const float z   = (y - m) * inv;
        ch[tid] = __expf(-z * z);
    }
    if (tid == 0) ch[NCH] = 0.0f;   // slack slot for predicated c+1 reads
    __syncthreads();

    // ---- Phase 4: re-read x (L2-hit, evict-first), gate, stream store ----
    const float4* __restrict__ x4 = (const float4*)xp;
    float4* __restrict__ o4 = (float4*)(out + base);

    #pragma unroll
    for (int b = 0; b < FULL_BATCHES; ++b) {
        const int i0 = tid + (4 * b) * NTHREADS;
        // 4 independent 128b loads in flight before any store
        float4 v0 = __ldcs(x4 + i0 + 0 * NTHREADS);
        float4 v1 = __ldcs(x4 + i0 + 1 * NTHREADS);
        float4 v2 = __ldcs(x4 + i0 + 2 * NTHREADS);
        float4 v3 = __ldcs(x4 + i0 + 3 * NTHREADS);
        #pragma unroll
        for (int k = 0; k < 4; ++k) {
            float4& v = (k == 0) ? v0 : (k == 1) ? v1 : (k == 2) ? v2 : v3;
            const int e = (i0 + k * NTHREADS) * 4;
            const int c = e / HW;            // constant div -> mul+shift
            const int r = e - c * HW;        // 0..48
            const float g0 = ch[c];
            const float gn = ch[c + 1];
            v.x *= g0;
            v.y *= (r < 48) ? g0 : gn;
            v.z *= (r < 47) ? g0 : gn;
            v.w *= (r < 46) ? g0 : gn;
            __stcs(o4 + i0 + k * NTHREADS, v);
        }
    }
    // remainder: SLAB4 - 12*512 = 128 float4s
    if (tid < REM_THREADS) {
        const int i = tid + 12 * NTHREADS;
        float4 v = __ldcs(x4 + i);
        const int e = i * 4;
        const int c = e / HW;
        const int r = e - c * HW;
        const float g0 = ch[c];
        const float gn = ch[c + 1];
        v.x *= g0;
        v.y *= (r < 48) ? g0 : gn;
        v.z *= (r < 47) ? g0 : gn;
        v.w *= (r < 46) ? g0 : gn;
        __stcs(o4 + i, v);
    }
}

extern "C" void kernel_launch(void* const* d_in, const int* in_sizes, int n_in,
                              void* d_out, int out_size)
{
    const float* x = (const float*)d_in[0];
    float* out = (float*)d_out;
    const int nblocks = in_sizes[0] / SLAB;   // 2048 samples
    ModelNew_25056839205377_kernel<<<nblocks, NTHREADS>>>(x, out);
}